// round 13
// baseline (speedup 1.0000x reference)
#include <cuda_runtime.h>

// CrossAttentionConditionInjection — analytic collapse, ONE kernel, zero
// duplicate weight reads.
//
// Math: K/V come from one condition token broadcast across seq => softmax
// weights are exactly 1/S (S=2048 pow2) => attn == v1 broadcast.
//   out[b,s,:] = Wo @ (Wv @ cond[b] + bv) + bo   (same vector for every s)
//
// R13: R12 issued 16MB of loads for 8MB distinct (rows read once per batch
// index). Now each block owns 8 DISTINCT Wv rows (dotted against BOTH cond
// vectors from one load) + stages 8 DISTINCT Wo rows in smem. Phase-1 DRAM
// request stream = exactly 8MB, all misses, across all 32 warps/block.

#define BDIM 1024
#define NB   2
#define NS   2048
#define GRID 128          // 1 block/SM -> co-resident, barrier-safe
#define TPB  1024

__device__ float    g_v1[NB * BDIM];
__device__ unsigned g_bar = 0;          // monotonic ticket counter (replay-safe)

__device__ __forceinline__ void grid_sync() {
    __syncthreads();
    if (threadIdx.x == 0) {
        __threadfence();
        unsigned ticket = atomicAdd(&g_bar, 1u);
        unsigned target = (ticket / GRID + 1u) * GRID;
        while (atomicAdd(&g_bar, 0u) < target)
            __nanosleep(64);
        __threadfence();
    }
    __syncthreads();
}

__global__ void __launch_bounds__(TPB, 1)
fused_kernel(const float* __restrict__ Wv, const float* __restrict__ cond,
             const float* __restrict__ bv, const float* __restrict__ Wo,
             const float* __restrict__ bo, float4* __restrict__ out) {
    __shared__ float4 s_wo[8 * 256];            // 8 Wo rows x 4KB = 32KB
    __shared__ float  s_part[16][2];            // half-row dots x 2 batches
    __shared__ float  s_o1[16];                 // o1[b][0..7] for this block

    const int warp = threadIdx.x >> 5;
    const int lane = threadIdx.x & 31;
    const int r0   = blockIdx.x * 8;            // this block's 8 weight rows

    // ---------------- Phase 1: pure-miss 8MB read, all warps ----------------
    if (warp < 16) {
        // mv: row r0 + (warp>>1), half h = warp&1. One W load, TWO dots.
        int rl = warp >> 1;
        int h  = warp & 1;
        const float4* W4 = reinterpret_cast<const float4*>(Wv + (size_t)(r0 + rl) * BDIM)
                           + h * 128;
        const float4* x0 = reinterpret_cast<const float4*>(cond) + h * 128;
        const float4* x1 = reinterpret_cast<const float4*>(cond + BDIM) + h * 128;
        float s0 = 0.f, s1 = 0.f;
#pragma unroll
        for (int i = 0; i < 4; ++i) {
            float4 wv = W4[lane + i * 32];
            float4 a  = x0[lane + i * 32];
            float4 c  = x1[lane + i * 32];
            s0 += wv.x * a.x + wv.y * a.y + wv.z * a.z + wv.w * a.w;
            s1 += wv.x * c.x + wv.y * c.y + wv.z * c.z + wv.w * c.w;
        }
#pragma unroll
        for (int off = 16; off; off >>= 1) {
            s0 += __shfl_xor_sync(0xffffffffu, s0, off);
            s1 += __shfl_xor_sync(0xffffffffu, s1, off);
        }
        if (lane == 0) { s_part[warp][0] = s0; s_part[warp][1] = s1; }
    } else {
        // stage: Wo row r0 + (j>>1), half h = j&1 -> smem.
        int j  = warp - 16;
        int rl = j >> 1;
        int h  = j & 1;
        const float4* W4 = reinterpret_cast<const float4*>(Wo + (size_t)(r0 + rl) * BDIM)
                           + h * 128;
#pragma unroll
        for (int i = 0; i < 4; ++i)
            s_wo[rl * 256 + h * 128 + lane + i * 32] = W4[lane + i * 32];
    }
    __syncthreads();

    // Combine halves, publish v1 (16 values: 8 rows x 2 batches).
    if (threadIdx.x < 16) {
        int rl = threadIdx.x >> 1;
        int b  = threadIdx.x & 1;
        g_v1[b * BDIM + r0 + rl] =
            s_part[rl * 2 + 0][b] + s_part[rl * 2 + 1][b] + bv[r0 + rl];
    }

    grid_sync();                                // all 2048 v1 values published

    // ------------- Phase 2: o1 from smem Wo + 8KB global v1 -------------
    if (warp < 16) {
        int rl = warp >> 1;
        int b  = warp & 1;
        const float4* v4 = reinterpret_cast<const float4*>(g_v1 + (size_t)b * BDIM);
        float sum = 0.f;
#pragma unroll
        for (int i = 0; i < 8; ++i) {
            float4 wv = s_wo[rl * 256 + lane + i * 32];
            float4 xv = v4[lane + i * 32];
            sum += wv.x * xv.x + wv.y * xv.y + wv.z * xv.z + wv.w * xv.w;
        }
#pragma unroll
        for (int off = 16; off; off >>= 1)
            sum += __shfl_xor_sync(0xffffffffu, sum, off);
        if (lane == 0) s_o1[b * 8 + rl] = sum + bo[r0 + rl];
    }
    __syncthreads();

    // ---- Phase 3: broadcast block's 32B chunk (8 d) x 2 b over all s ----
    // (b,s,c) tuples: 2 * 2048 * 2 = 8192; 8 per thread. c = float4 within
    // the 8-float chunk.
    const float4* o14 = reinterpret_cast<const float4*>(s_o1);
    float4 q0 = o14[0], q1 = o14[1], q2 = o14[2], q3 = o14[3];
    const int dbase = r0 >> 2;                  // float4 offset of d-chunk
#pragma unroll
    for (int k = 0; k < 8; ++k) {
        int i = k * TPB + threadIdx.x;
        int c = i & 1;
        int s = (i >> 1) & (NS - 1);
        int b = i >> 12;
        float4 val = (b == 0) ? (c == 0 ? q0 : q1) : (c == 0 ? q2 : q3);
        size_t addr = (size_t)b * NS * (BDIM / 4) + (size_t)s * (BDIM / 4)
                    + dbase + c;
        __stcs(out + addr, val);
    }
}

extern "C" void kernel_launch(void* const* d_in, const int* in_sizes, int n_in,
                              void* d_out, int out_size) {
    // metadata order: hidden_states, condition, Wq, bq, Wk, bk, Wv, bv, Wo, bo
    const float* cond = (const float*)d_in[1];
    const float* Wv   = (const float*)d_in[6];
    const float* bv   = (const float*)d_in[7];
    const float* Wo   = (const float*)d_in[8];
    const float* bo   = (const float*)d_in[9];

    fused_kernel<<<GRID, TPB>>>(Wv, cond, bv, Wo, bo, (float4*)d_out);
}

// round 14
// speedup vs baseline: 1.0026x; 1.0026x over previous
#include <cuda_runtime.h>

// CrossAttentionConditionInjection — analytic collapse, ONE kernel,
// PURE-STREAMING weight load phase.
//
// Math: K/V come from one condition token broadcast across seq => softmax
// weights are exactly 1/S (S=2048 pow2) => attn == v1 broadcast.
//   out[b,s,:] = Wo @ (Wv @ cond[b] + bv) + bo   (same vector for every s)
//
// R14 theory: every kernel whose warps interleave compute/L1-hits with the
// DRAM miss stream reads at ~750 GB/s; the only >1.4TB/s observation (R11)
// had pure load-only streaming warps. So: phase 1 is NOTHING but
// LDG.128->STS for this block's 8 Wv + 8 Wo rows (64KB smem, zero
// duplication chip-wide); all dots happen afterwards from smem.

#define BDIM 1024
#define NB   2
#define NS   2048
#define GRID 128          // 1 block/SM -> co-resident, barrier-safe
#define TPB  1024
#define SMEM_BYTES (16 * BDIM * 4)      // 16 rows x 4KB = 64KB

__device__ float    g_v1[NB * BDIM];
__device__ unsigned g_bar = 0;          // monotonic ticket counter (replay-safe)

__device__ __forceinline__ void grid_sync() {
    __syncthreads();
    if (threadIdx.x == 0) {
        __threadfence();
        unsigned ticket = atomicAdd(&g_bar, 1u);
        unsigned target = (ticket / GRID + 1u) * GRID;
        while (atomicAdd(&g_bar, 0u) < target)
            __nanosleep(64);
        __threadfence();
    }
    __syncthreads();
}

__global__ void __launch_bounds__(TPB, 1)
fused_kernel(const float* __restrict__ Wv, const float* __restrict__ cond,
             const float* __restrict__ bv, const float* __restrict__ Wo,
             const float* __restrict__ bo, float4* __restrict__ out) {
    extern __shared__ float4 s_w[];     // [16][256]: rows 0-7 Wv, 8-15 Wo
    __shared__ float s_o1[16];          // o1 chunk: [b][0..7]

    const int warp = threadIdx.x >> 5;
    const int lane = threadIdx.x & 31;
    const int r0   = blockIdx.x * 8;    // this block's 8 rows (of each W)

    // ---- Phase 1: PURE streaming. warp w: row w>>1, half h=w&1 (2KB). ----
    {
        int row = warp >> 1;            // 0..15
        int h   = warp & 1;
        const float* src = (row < 8) ? (Wv + (size_t)(r0 + row) * BDIM)
                                     : (Wo + (size_t)(r0 + row - 8) * BDIM);
        const float4* s4 = reinterpret_cast<const float4*>(src) + h * 128;
        float4* dst = s_w + row * 256 + h * 128;
#pragma unroll
        for (int i = 0; i < 4; ++i)
            dst[lane + i * 32] = __ldcg(s4 + lane + i * 32);
    }
    __syncthreads();

    // ---- Phase 2: v1 dots from smem Wv + L2-hot cond ----
    if (warp < 16) {
        int rl = warp >> 1;             // 0..7
        int b  = warp & 1;
        const float4* w4 = s_w + rl * 256;
        const float4* x4 = reinterpret_cast<const float4*>(cond + (size_t)b * BDIM);
        float sum = 0.f;
#pragma unroll
        for (int i = 0; i < 8; ++i) {
            float4 wv = w4[lane + i * 32];
            float4 xv = x4[lane + i * 32];
            sum += wv.x * xv.x + wv.y * xv.y + wv.z * xv.z + wv.w * xv.w;
        }
#pragma unroll
        for (int off = 16; off; off >>= 1)
            sum += __shfl_xor_sync(0xffffffffu, sum, off);
        if (lane == 0)
            g_v1[b * BDIM + r0 + rl] = sum + bv[r0 + rl];
    }

    grid_sync();                        // all 2048 v1 values published

    // ---- Phase 3: o1 dots from smem Wo + 8KB global v1 ----
    if (warp < 16) {
        int rl = warp >> 1;
        int b  = warp & 1;
        const float4* w4 = s_w + (8 + rl) * 256;
        const float4* v4 = reinterpret_cast<const float4*>(g_v1 + (size_t)b * BDIM);
        float sum = 0.f;
#pragma unroll
        for (int i = 0; i < 8; ++i) {
            float4 wv = w4[lane + i * 32];
            float4 xv = v4[lane + i * 32];
            sum += wv.x * xv.x + wv.y * xv.y + wv.z * xv.z + wv.w * xv.w;
        }
#pragma unroll
        for (int off = 16; off; off >>= 1)
            sum += __shfl_xor_sync(0xffffffffu, sum, off);
        if (lane == 0) s_o1[b * 8 + rl] = sum + bo[r0 + rl];
    }
    __syncthreads();

    // ---- Phase 4: broadcast block's 32B chunk x 2 batches over all s ----
    // 8192 (c,s,b) tuples, 8 per thread (validated in R13).
    const float4* o14 = reinterpret_cast<const float4*>(s_o1);
    float4 q0 = o14[0], q1 = o14[1], q2 = o14[2], q3 = o14[3];
    const int dbase = r0 >> 2;
#pragma unroll
    for (int k = 0; k < 8; ++k) {
        int i = k * TPB + threadIdx.x;
        int c = i & 1;
        int s = (i >> 1) & (NS - 1);
        int b = i >> 12;
        float4 val = (b == 0) ? (c == 0 ? q0 : q1) : (c == 0 ? q2 : q3);
        size_t addr = (size_t)b * NS * (BDIM / 4) + (size_t)s * (BDIM / 4)
                    + dbase + c;
        __stcs(out + addr, val);
    }
}

extern "C" void kernel_launch(void* const* d_in, const int* in_sizes, int n_in,
                              void* d_out, int out_size) {
    // metadata order: hidden_states, condition, Wq, bq, Wk, bk, Wv, bv, Wo, bo
    const float* cond = (const float*)d_in[1];
    const float* Wv   = (const float*)d_in[6];
    const float* bv   = (const float*)d_in[7];
    const float* Wo   = (const float*)d_in[8];
    const float* bo   = (const float*)d_in[9];

    static int attr_done = 0;           // idempotent opt-in to 64KB dyn smem
    if (!attr_done) {
        cudaFuncSetAttribute(fused_kernel,
                             cudaFuncAttributeMaxDynamicSharedMemorySize,
                             SMEM_BYTES);
        attr_done = 1;
    }
    fused_kernel<<<GRID, TPB, SMEM_BYTES>>>(Wv, cond, bv, Wo, bo,
                                            (float4*)d_out);
}

// round 15
// speedup vs baseline: 1.0129x; 1.0103x over previous
#include <cuda_runtime.h>

// CrossAttentionConditionInjection — analytic collapse, 3 kernels,
// MANY-SMALL-BLOCKS matvecs (outstanding-miss scaling bet).
//
// Math: K/V come from one condition token broadcast across seq => softmax
// weights are exactly 1/S (S=2048 pow2) => attn == v1 broadcast.
//   out[b,s,:] = Wo @ (Wv @ cond[b] + bv) + bo   (same vector for every s)
//
// R15 theory: read BW scales with resident BLOCKS/SM (R11: 2.6 blk/SM ->
// 1412 GB/s vs 1.0-1.7 blk/SM -> ~750). So each matvec = 1024 blocks x 64
// threads (6.9 blk/SM): block = one W row; 2 warps x half-row; each warp
// dual-dots both batch vectors from ONE weight load (zero duplicate reads).

#define BDIM 1024
#define NB   2
#define NS   2048

__device__ float g_v1[NB * BDIM];
__device__ float g_o1[NB * BDIM];

// ---------------------------------------------------------------------------
// Block = weight row `blockIdx.x`. Warp h in {0,1} covers half-row h:
// 4 float4 W loads (the only DRAM misses), dotted against both x vectors.
// y[b*D + row] = dot(W[row,:], x[b,:]) + bias[row]
// ---------------------------------------------------------------------------
__device__ __forceinline__ void mv_dual(const float* __restrict__ W,
                                        const float* __restrict__ x,  // [2][D]
                                        const float* __restrict__ bias,
                                        float* __restrict__ y) {      // [2][D]
    __shared__ float part[2][2];                // [half][b]
    const int lane = threadIdx.x & 31;
    const int half = threadIdx.x >> 5;          // 0 or 1
    const int row  = blockIdx.x;                // 0..1023

    const float4* W4 = reinterpret_cast<const float4*>(W + (size_t)row * BDIM)
                       + half * 128;
    const float4* x0 = reinterpret_cast<const float4*>(x) + half * 128;
    const float4* x1 = reinterpret_cast<const float4*>(x + BDIM) + half * 128;

    float s0 = 0.f, s1 = 0.f;
#pragma unroll
    for (int i = 0; i < 4; ++i) {
        float4 w = W4[lane + i * 32];           // DRAM miss stream
        float4 a = x0[lane + i * 32];           // L2-hot (8KB shared by all)
        float4 c = x1[lane + i * 32];
        s0 += w.x * a.x + w.y * a.y + w.z * a.z + w.w * a.w;
        s1 += w.x * c.x + w.y * c.y + w.z * c.z + w.w * c.w;
    }
#pragma unroll
    for (int off = 16; off; off >>= 1) {
        s0 += __shfl_xor_sync(0xffffffffu, s0, off);
        s1 += __shfl_xor_sync(0xffffffffu, s1, off);
    }
    if (lane == 0) { part[half][0] = s0; part[half][1] = s1; }
    __syncthreads();
    if (threadIdx.x < 2) {                      // threadIdx.x == b
        y[threadIdx.x * BDIM + row] =
            part[0][threadIdx.x] + part[1][threadIdx.x] + bias[row];
    }
}

__global__ void __launch_bounds__(64) k1_mv1(const float* __restrict__ Wv,
                                             const float* __restrict__ cond,
                                             const float* __restrict__ bv) {
    mv_dual(Wv, cond, bv, g_v1);
}

__global__ void __launch_bounds__(64) k2_mv2(const float* __restrict__ Wo,
                                             const float* __restrict__ bo) {
    mv_dual(Wo, g_v1, bo, g_o1);
}

// K3: out[b,s,:] = o1[b,:]. One coalesced float4 streaming store per thread.
__global__ void __launch_bounds__(512) k3_bcast(float4* __restrict__ out) {
    const float4* o1 = reinterpret_cast<const float4*>(g_o1);
    int i  = blockIdx.x * blockDim.x + threadIdx.x;
    int b  = i >> 19;          // / (S*D/4)
    int d4 = i & 255;          // % (D/4)
    __stcs(out + i, o1[(b << 8) + d4]);
}

extern "C" void kernel_launch(void* const* d_in, const int* in_sizes, int n_in,
                              void* d_out, int out_size) {
    // metadata order: hidden_states, condition, Wq, bq, Wk, bk, Wv, bv, Wo, bo
    const float* cond = (const float*)d_in[1];
    const float* Wv   = (const float*)d_in[6];
    const float* bv   = (const float*)d_in[7];
    const float* Wo   = (const float*)d_in[8];
    const float* bo   = (const float*)d_in[9];

    k1_mv1<<<BDIM, 64>>>(Wv, cond, bv);
    k2_mv2<<<BDIM, 64>>>(Wo, bo);
    k3_bcast<<<(NB * NS * BDIM / 4) / 512, 512>>>((float4*)d_out);
}